// round 16
// baseline (speedup 1.0000x reference)
#include <cuda_runtime.h>
#include <math.h>

#define N 448
#define NP (N*N)
#define NROT 21
#define NSAD_BLK 16
#define PI_D 3.14159265358979323846

typedef unsigned long long u64;

// ---------------- f32x2 helpers ----------------
#define FMA2(acc, a, b) asm("fma.rn.f32x2 %0, %1, %2, %0;" : "+l"(acc) : "l"(a), "l"(b))
__device__ __forceinline__ u64 packf2(float lo, float hi) {
    u64 r; asm("mov.b64 %0, {%1, %2};" : "=l"(r) : "f"(lo), "f"(hi)); return r;
}
__device__ __forceinline__ void unpackf2(u64 v, float& lo, float& hi) {
    asm("mov.b64 {%0, %1}, %2;" : "=f"(lo), "=f"(hi) : "l"(v));
}

// old swizzle (tail kernel): 64B-per-lane stride granules
#define SWZ(j) ((j) ^ (((j) >> 3) & 3))
// Karatsuba swizzle: 32B-per-lane stride -> 2-way conflict fixed by bit3 parity
#define SWZ2(g) ((g) ^ (((g) >> 3) & 1))

// ---------------- device global scratch ----------------
__device__ __align__(16) float g_A[NROT*NP];
__device__ __align__(16) float g_B[NROT*NP];
__device__ __align__(16) float g_rot[NROT*NP];
__device__ __align__(16) u64   g_kxp3[NROT*224*672];  // [rot][rp][ke|ko|ks] pair streams
__device__ __align__(16) u64   g_kyp3[NROT*224*672];
__device__ __align__(16) u64   g_fkp[2*224*448];      // old-style tables (tail path)
__device__ __align__(16) u64   g_t4p[4*448];
__device__ double g_partial[NROT*NSAD_BLK*25];
__device__ float  g_res[4];
__device__ __align__(16) float g_w1[NP], g_w2[NP];

// ---------------- circulant kernel values ----------------
__device__ __forceinline__ float cr_from(int m, float sf, float S) {
    float w0 = (float)m - sf;
    float w  = (w0 > 224.0f) ? (w0 - 448.0f) : w0;
    if (fabsf(w) < 1e-7f) return 1.0f;
    float num = (m & 1) ? S : -S;
    float arg = w * (1.0f/448.0f);
    return num * cospif(arg) / (448.0f * sinpif(arg));
}
__device__ __forceinline__ float ci_from(int m, float sf, float S) {
    return ((m & 1) ? -S : S) * (1.0f/448.0f);
}
__device__ __forceinline__ int mod_si(double si) {
    int sii = (int)si;
    return ((sii % 448) + 448) % 448;
}

// ---------------- build Karatsuba pair tables: [ke|ko|ks] per row-pair ----------------
__global__ void build_tables_k() {
    __shared__ float sf0, S0, sf1, S1; __shared__ int m00, m01;
    int rp = blockIdx.x, kk = blockIdx.y, type = blockIdx.z;
    if (threadIdx.x < 2) {
        double th = (double)(kk - 10) * (PI_D / 180.0);
        double c  = (type == 0) ? -tan(th * 0.5) : sin(th);
        int row = 2*rp + threadIdx.x;
        double s  = c * ((double)row - 223.5);
        double si = floor(s);
        float sf  = (float)(s - si);
        if (threadIdx.x == 0) { sf0 = sf; S0 = sinpif(sf); m00 = mod_si(si); }
        else                  { sf1 = sf; S1 = sinpif(sf); m01 = mod_si(si); }
    }
    __syncthreads();
    int q = threadIdx.x;               // 0..223
    int ue = 2*q, uo = 2*q + 1;
    int mae = ue - m00; if (mae < 0) mae += 448;
    int mao = uo - m00; if (mao < 0) mao += 448;
    int mbe = ue - m01; if (mbe < 0) mbe += 448;
    int mbo = uo - m01; if (mbo < 0) mbo += 448;
    float ke0 = cr_from(mae, sf0, S0), ko0 = cr_from(mao, sf0, S0);
    float ke1 = cr_from(mbe, sf1, S1), ko1 = cr_from(mbo, sf1, S1);
    u64* dst = ((type == 0) ? g_kxp3 : g_kyp3) + ((size_t)kk*224 + rp)*672;
    dst[q]       = packf2(ke0, ke1);
    dst[224 + q] = packf2(ko0, ko1);
    dst[448 + q] = packf2(ke0 + ko0, ke1 + ko1);
}

// ---------------- merged tail table builder ----------------
__global__ void build_final_all() {
    int type = blockIdx.y;
    if (type < 2) {
        __shared__ float sf0, S0, sf1, S1; __shared__ int m00, m01;
        int rp = blockIdx.x;
        if (threadIdx.x < 2) {
            double th = -(double)g_res[2];
            double c  = (type == 0) ? -tan(th * 0.5) : sin(th);
            int row = 2*rp + threadIdx.x;
            double s  = c * ((double)row - 223.5);
            double si = floor(s);
            float sf  = (float)(s - si);
            if (threadIdx.x == 0) { sf0 = sf; S0 = sinpif(sf); m00 = mod_si(si); }
            else                  { sf1 = sf; S1 = sinpif(sf); m01 = mod_si(si); }
        }
        __syncthreads();
        int u = threadIdx.x;
        int ma = u - m00; if (ma < 0) ma += 448;
        int mb = u - m01; if (mb < 0) mb += 448;
        g_fkp[(size_t)type*224*448 + (size_t)rp*448 + u] =
            packf2(cr_from(ma, sf0, S0), cr_from(mb, sf1, S1));
    } else {
        if (blockIdx.x != 0) return;
        __shared__ float sfx, Sx, sfy, Sy; __shared__ int m0x, m0y;
        if (threadIdx.x == 0) {
            double sx = -(double)g_res[0];
            double sy = -(double)g_res[1];
            double six = floor(sx), siy = floor(sy);
            sfx = (float)(sx - six); Sx = sinpif(sfx); m0x = mod_si(six);
            sfy = (float)(sy - siy); Sy = sinpif(sfy); m0y = mod_si(siy);
        }
        __syncthreads();
        int u = threadIdx.x;
        int mx = u - m0x; if (mx < 0) mx += 448;
        int my = u - m0y; if (my < 0) my += 448;
        float crx = cr_from(mx, sfx, Sx), cix = ci_from(mx, sfx, Sx);
        float cry = cr_from(my, sfy, Sy), ciy = ci_from(my, sfy, Sy);
        g_t4p[0*448 + u] = packf2(crx, crx);
        g_t4p[1*448 + u] = packf2(cix, cix);
        g_t4p[2*448 + u] = packf2(cry, cry);
        g_t4p[3*448 + u] = packf2(ciy, ciy);
    }
}

// ============ Karatsuba conv step macros (taps from smem) ============
// Ring-8 (A/G, 4 accs): loads -> slots (B+t)%8; taps: acc i, c_dd -> slot (B+4+i-dd)%8.
#define CSTEP8(B, P0,P1,P2,P3) do { \
    int sw = su; if (sw >= 224) sw -= 224; \
    int gg = SWZ2(sw >> 1); \
    ulonglong2 va = ip2[gg], vb = ip2[gg ^ 1]; \
    W[((B)+0)%8]=va.x; W[((B)+1)%8]=va.y; W[((B)+2)%8]=vb.x; W[((B)+3)%8]=vb.y; \
    ulonglong2 k01 = kp2[0], k23 = kp2[1]; kp2 += 2; \
    u64 c0=k01.x, c1=k01.y, c2=k23.x, c3=k23.y; \
    FMA2(P0, W[((B)+4)%8], c0); FMA2(P1, W[((B)+5)%8], c0); FMA2(P2, W[((B)+6)%8], c0); FMA2(P3, W[((B)+7)%8], c0); \
    FMA2(P1, W[((B)+4)%8], c1); FMA2(P2, W[((B)+5)%8], c1); FMA2(P3, W[((B)+6)%8], c1); \
    FMA2(P2, W[((B)+4)%8], c2); FMA2(P3, W[((B)+5)%8], c2); \
    FMA2(P3, W[((B)+4)%8], c3); \
    FMA2(P0, W[((B)+3)%8], c1); \
    FMA2(P1, W[((B)+3)%8], c2); FMA2(P0, W[((B)+2)%8], c2); \
    FMA2(P2, W[((B)+3)%8], c3); FMA2(P1, W[((B)+2)%8], c3); FMA2(P0, W[((B)+1)%8], c3); \
    su -= 4; \
} while(0)

// Ring-8 (E, 5 accs targeting p0-1..p0+3): taps: acc i, c_dd -> slot (B+3+i-dd)%8.
// Live span per step is exactly 8 slots (loads B+0..3, old B+4..7), so ring-8
// suffices — ring-12 wasted 8 registers. Identical (i,dd) sequence -> bit-identical.
#define CSTEP8E(B, Q0,Q1,Q2,Q3,Q4) do { \
    int sw = su; if (sw >= 224) sw -= 224; \
    int gg = SWZ2(sw >> 1); \
    ulonglong2 va = ip2[gg], vb = ip2[gg ^ 1]; \
    W[((B)+0)%8]=va.x; W[((B)+1)%8]=va.y; W[((B)+2)%8]=vb.x; W[((B)+3)%8]=vb.y; \
    ulonglong2 k01 = kp2[0], k23 = kp2[1]; kp2 += 2; \
    u64 c0=k01.x, c1=k01.y, c2=k23.x, c3=k23.y; \
    FMA2(Q1, W[((B)+4)%8], c0); FMA2(Q2, W[((B)+5)%8], c0); FMA2(Q3, W[((B)+6)%8], c0); FMA2(Q4, W[((B)+7)%8], c0); \
    FMA2(Q2, W[((B)+4)%8], c1); FMA2(Q3, W[((B)+5)%8], c1); FMA2(Q4, W[((B)+6)%8], c1); \
    FMA2(Q3, W[((B)+4)%8], c2); FMA2(Q4, W[((B)+5)%8], c2); \
    FMA2(Q4, W[((B)+4)%8], c3); \
    FMA2(Q0, W[((B)+3)%8], c0); \
    FMA2(Q1, W[((B)+3)%8], c1); FMA2(Q0, W[((B)+2)%8], c1); \
    FMA2(Q2, W[((B)+3)%8], c2); FMA2(Q1, W[((B)+2)%8], c2); FMA2(Q0, W[((B)+1)%8], c2); \
    FMA2(Q3, W[((B)+3)%8], c3); FMA2(Q2, W[((B)+2)%8], c3); FMA2(Q1, W[((B)+1)%8], c3); FMA2(Q0, W[((B)+0)%8], c3); \
    su -= 4; \
} while(0)

#define STG_PITCH 456

// ---------------- Karatsuba row-pair shear (RPB=4, 224 threads, 5 blocks/SM) ----------------
template<int WT>
__global__ void __launch_bounds__(224, 5) shear_k(
    const float* __restrict__ in, int inImgStride,
    float* __restrict__ out,
    const u64* __restrict__ tab, int y0off)
{
    __shared__ __align__(16) u64 s_in[4*672];   // per rp: [se|so|ss], each 224 u64, SWZ2
    __shared__ __align__(16) u64 s_k[4*672];    // per rp: [ke|ko|ks]
    int b  = blockIdx.y;
    int bx = blockIdx.x + y0off;
    int y0 = bx * 8;
    int t  = threadIdx.x;

    const float* inb = in + (size_t)b*inImgStride + (size_t)y0*N;
    const u64*   tbb = tab + (size_t)b*(224*672) + (size_t)(bx*4)*672;

    // kernel streams: 4 rp x 336 ulonglong2
    #pragma unroll
    for (int i = t; i < 1344; i += 224) {
        int rp2 = i / 336, jj = i % 336;
        ((ulonglong2*)(s_k + rp2*672))[jj] =
            ((const ulonglong2*)(tbb + (size_t)rp2*672))[jj];
    }
    // input streams: per rp, p in [0,224): se=in[2p], so=in[2p+1], ss=sum
    #pragma unroll
    for (int i = t; i < 896; i += 224) {
        int rp2 = i / 224, p = i % 224;
        const float* r0 = inb + (size_t)(2*rp2)*N;
        float2 a = *(const float2*)(r0 + 2*p);
        float2 c = *(const float2*)(r0 + N + 2*p);
        int g = p >> 1;
        int phys = ((g ^ ((g >> 3) & 1)) << 1) | (p & 1);
        u64* base = s_in + rp2*672;
        base[phys]       = packf2(a.x, c.x);
        base[224 + phys] = packf2(a.y, c.y);
        base[448 + phys] = packf2(a.x + a.y, c.x + c.y);
    }
    __syncthreads();

    int rp = t / 56, li = t % 56;
    int p0 = li * 4;
    int x0 = li * 8;

    u64 W[8];
    u64 A0=0,A1=0,A2=0,A3=0;
    u64 E0=0,E1=0,E2=0,E3=0,E4=0;
    u64 G0=0,G1=0,G2=0,G3=0;
    const ulonglong2* ip2;
    const ulonglong2* kp2;
    int su;
    int gi = SWZ2(p0 >> 1);

    // ---- A = ke (*) se ----
    ip2 = (const ulonglong2*)(s_in + rp*672);
    kp2 = (const ulonglong2*)(s_k + rp*672);
    { ulonglong2 v0 = ip2[gi], v1 = ip2[gi ^ 1];
      W[0]=v0.x; W[1]=v0.y; W[2]=v1.x; W[3]=v1.y; }
    su = p0 + 220;
    for (int m = 0; m < 28; ++m) { CSTEP8(4, A0,A1,A2,A3); CSTEP8(0, A0,A1,A2,A3); }

    // ---- E = ko (*) so  (5 accs: p0-1 .. p0+3), ring-8 ----
    ip2 = (const ulonglong2*)(s_in + rp*672 + 224);
    kp2 = (const ulonglong2*)(s_k + rp*672 + 224);
    { ulonglong2 v0 = ip2[gi], v1 = ip2[gi ^ 1];
      W[0]=v0.x; W[1]=v0.y; W[2]=v1.x; W[3]=v1.y; }
    su = p0 + 220;
    for (int m = 0; m < 28; ++m) { CSTEP8E(4, E0,E1,E2,E3,E4); CSTEP8E(0, E0,E1,E2,E3,E4); }

    // ---- G = ks (*) ss ----
    ip2 = (const ulonglong2*)(s_in + rp*672 + 448);
    kp2 = (const ulonglong2*)(s_k + rp*672 + 448);
    { ulonglong2 v0 = ip2[gi], v1 = ip2[gi ^ 1];
      W[0]=v0.x; W[1]=v0.y; W[2]=v1.x; W[3]=v1.y; }
    su = p0 + 220;
    for (int m = 0; m < 28; ++m) { CSTEP8(4, G0,G1,G2,G3); CSTEP8(0, G0,G1,G2,G3); }

    // ---- combine: out_e[i] = A_i + E_i ; out_o[i] = G_i - A_i - E_{i+1} ----
    float a0l,a0h,a1l,a1h,a2l,a2h,a3l,a3h;
    float e0l,e0h,e1l,e1h,e2l,e2h,e3l,e3h,e4l,e4h;
    float g0l,g0h,g1l,g1h,g2l,g2h,g3l,g3h;
    unpackf2(A0,a0l,a0h); unpackf2(A1,a1l,a1h); unpackf2(A2,a2l,a2h); unpackf2(A3,a3l,a3h);
    unpackf2(E0,e0l,e0h); unpackf2(E1,e1l,e1h); unpackf2(E2,e2l,e2h); unpackf2(E3,e3l,e3h); unpackf2(E4,e4l,e4h);
    unpackf2(G0,g0l,g0h); unpackf2(G1,g1l,g1h); unpackf2(G2,g2l,g2h); unpackf2(G3,g3l,g3h);

    float4 r0a, r0b, r1a, r1b;
    r0a.x = a0l + e0l;  r0a.y = g0l - a0l - e1l;
    r0a.z = a1l + e1l;  r0a.w = g1l - a1l - e2l;
    r0b.x = a2l + e2l;  r0b.y = g2l - a2l - e3l;
    r0b.z = a3l + e3l;  r0b.w = g3l - a3l - e4l;
    r1a.x = a0h + e0h;  r1a.y = g0h - a0h - e1h;
    r1a.z = a1h + e1h;  r1a.w = g1h - a1h - e2h;
    r1b.x = a2h + e2h;  r1b.y = g2h - a2h - e3h;
    r1b.z = a3h + e3h;  r1b.w = g3h - a3h - e4h;

    if (WT == 0) {
        float* o0 = out + (size_t)b*NP + (size_t)(y0 + 2*rp)*N + x0;
        ((float4*)o0)[0] = r0a; ((float4*)o0)[1] = r0b;
        ((float4*)(o0 + N))[0] = r1a; ((float4*)(o0 + N))[1] = r1b;
    } else {
        __syncthreads();
        float* stg = (float*)s_in;
        float* sr = stg + (size_t)(2*rp)*STG_PITCH + x0;
        ((float4*)sr)[0] = r0a; ((float4*)sr)[1] = r0b;
        ((float4*)(sr + STG_PITCH))[0] = r1a; ((float4*)(sr + STG_PITCH))[1] = r1b;
        __syncthreads();
        float* ob = out + (size_t)b*NP + y0;
        #pragma unroll
        for (int c = t; c < 448; c += 224) {
            const float* sc = stg + c;
            float4 va, vb;
            va.x = sc[0*STG_PITCH]; va.y = sc[1*STG_PITCH];
            va.z = sc[2*STG_PITCH]; va.w = sc[3*STG_PITCH];
            vb.x = sc[4*STG_PITCH]; vb.y = sc[5*STG_PITCH];
            vb.z = sc[6*STG_PITCH]; vb.w = sc[7*STG_PITCH];
            float* op = ob + (size_t)c*N;
            ((float4*)op)[0] = va;
            ((float4*)op)[1] = vb;
        }
    }
}

// ---------------- old pipelined shear (tail path, RPB=2) ----------------
#define STEPP(B,c0,c1,c2,c3,n0,n1,n2,n3) do { \
    int sj = SWZ(j); \
    ulonglong2 va = ip2[sj], vb = ip2[sj ^ 1]; \
    { ulonglong2 t0 = kp2[0], t1 = kp2[1]; n0=t0.x; n1=t0.y; n2=t1.x; n3=t1.y; kp2 += 2; } \
    W[((B)+8)%12]=va.x; W[((B)+9)%12]=va.y; W[((B)+10)%12]=vb.x; W[((B)+11)%12]=vb.y; \
    FMA2(A0, W[((B)+12)%12], c0); FMA2(A1, W[((B)+13)%12], c0); FMA2(A2, W[((B)+14)%12], c0); FMA2(A3, W[((B)+15)%12], c0); \
    FMA2(A4, W[((B)+16)%12], c0); FMA2(A5, W[((B)+17)%12], c0); FMA2(A6, W[((B)+18)%12], c0); FMA2(A7, W[((B)+19)%12], c0); \
    FMA2(A1, W[((B)+12)%12], c1); FMA2(A2, W[((B)+13)%12], c1); FMA2(A3, W[((B)+14)%12], c1); FMA2(A4, W[((B)+15)%12], c1); \
    FMA2(A5, W[((B)+16)%12], c1); FMA2(A6, W[((B)+17)%12], c1); FMA2(A7, W[((B)+18)%12], c1); \
    FMA2(A2, W[((B)+12)%12], c2); FMA2(A3, W[((B)+13)%12], c2); FMA2(A4, W[((B)+14)%12], c2); FMA2(A5, W[((B)+15)%12], c2); \
    FMA2(A6, W[((B)+16)%12], c2); FMA2(A7, W[((B)+17)%12], c2); \
    FMA2(A3, W[((B)+12)%12], c3); FMA2(A4, W[((B)+13)%12], c3); FMA2(A5, W[((B)+14)%12], c3); \
    FMA2(A6, W[((B)+15)%12], c3); FMA2(A7, W[((B)+16)%12], c3); \
    FMA2(A0, W[((B)+11)%12], c1); \
    FMA2(A1, W[((B)+11)%12], c2); FMA2(A0, W[((B)+10)%12], c2); \
    FMA2(A2, W[((B)+11)%12], c3); FMA2(A1, W[((B)+10)%12], c3); FMA2(A0, W[((B)+9)%12],  c3); \
    j -= 2; \
} while(0)

#define STEPL(B,c0,c1,c2,c3) do { \
    int sj = SWZ(j); \
    ulonglong2 va = ip2[sj], vb = ip2[sj ^ 1]; \
    W[((B)+8)%12]=va.x; W[((B)+9)%12]=va.y; W[((B)+10)%12]=vb.x; W[((B)+11)%12]=vb.y; \
    FMA2(A0, W[((B)+12)%12], c0); FMA2(A1, W[((B)+13)%12], c0); FMA2(A2, W[((B)+14)%12], c0); FMA2(A3, W[((B)+15)%12], c0); \
    FMA2(A4, W[((B)+16)%12], c0); FMA2(A5, W[((B)+17)%12], c0); FMA2(A6, W[((B)+18)%12], c0); FMA2(A7, W[((B)+19)%12], c0); \
    FMA2(A1, W[((B)+12)%12], c1); FMA2(A2, W[((B)+13)%12], c1); FMA2(A3, W[((B)+14)%12], c1); FMA2(A4, W[((B)+15)%12], c1); \
    FMA2(A5, W[((B)+16)%12], c1); FMA2(A6, W[((B)+17)%12], c1); FMA2(A7, W[((B)+18)%12], c1); \
    FMA2(A2, W[((B)+12)%12], c2); FMA2(A3, W[((B)+13)%12], c2); FMA2(A4, W[((B)+14)%12], c2); FMA2(A5, W[((B)+15)%12], c2); \
    FMA2(A6, W[((B)+16)%12], c2); FMA2(A7, W[((B)+17)%12], c2); \
    FMA2(A3, W[((B)+12)%12], c3); FMA2(A4, W[((B)+13)%12], c3); FMA2(A5, W[((B)+14)%12], c3); \
    FMA2(A6, W[((B)+15)%12], c3); FMA2(A7, W[((B)+16)%12], c3); \
    FMA2(A0, W[((B)+11)%12], c1); \
    FMA2(A1, W[((B)+11)%12], c2); FMA2(A0, W[((B)+10)%12], c2); \
    FMA2(A2, W[((B)+11)%12], c3); FMA2(A1, W[((B)+10)%12], c3); FMA2(A0, W[((B)+9)%12],  c3); \
    j -= 2; \
} while(0)

template<int RPB, int WT>
__global__ void __launch_bounds__(56*RPB, 8) shear_t(
    const float* __restrict__ in, int inImgStride,
    float* __restrict__ out,
    const u64* __restrict__ tab, int tabImgStride, int tabRpStride)
{
    __shared__ __align__(16) u64 s_in[RPB*896];
    __shared__ __align__(16) u64 s_k[RPB*448];
    const int NT = 56*RPB;
    int b  = blockIdx.y;
    int y0 = blockIdx.x * (2*RPB);
    int t  = threadIdx.x;

    const float* inb = in + (size_t)b*inImgStride + (size_t)y0*N;
    const u64*   tbb = tab + (size_t)b*tabImgStride + (size_t)(blockIdx.x*RPB)*tabRpStride;

    #pragma unroll
    for (int idx = t; idx < RPB*224; idx += NT) {
        int rp2 = idx / 224, jj = idx % 224;
        ((ulonglong2*)(s_k + rp2*448))[jj] =
            ((const ulonglong2*)(tbb + (size_t)rp2*tabRpStride))[jj];
    }
    #pragma unroll
    for (int idx = t; idx < RPB*448; idx += NT) {
        int rp2 = idx / 448, j = idx % 448;
        int c0 = 2*j; if (c0 >= 448) c0 -= 448;
        const float* r0 = inb + (size_t)(2*rp2)*N;
        float2 a = *(const float2*)(r0 + c0);
        float2 c = *(const float2*)(r0 + N + c0);
        ulonglong2 p; p.x = packf2(a.x, c.x); p.y = packf2(a.y, c.y);
        ((ulonglong2*)(s_in + rp2*896))[SWZ(j)] = p;
    }
    __syncthreads();

    int rp = t / 56, li = t % 56;
    int x0 = li * 8;
    const ulonglong2* ip2 = (const ulonglong2*)(s_in + rp*896);
    const ulonglong2* kp2 = (const ulonglong2*)(s_k + rp*448);

    u64 A0=0,A1=0,A2=0,A3=0,A4=0,A5=0,A6=0,A7=0;
    u64 W[12];
    {
        int j0 = 4*li + 224;
        int s0 = SWZ(j0);
        ulonglong2 v0 = ip2[s0],     v1 = ip2[s0 ^ 1];
        ulonglong2 v2 = ip2[s0 ^ 2], v3 = ip2[s0 ^ 3];
        W[4]=v0.x; W[5]=v0.y; W[6]=v1.x; W[7]=v1.y;
        W[8]=v2.x; W[9]=v2.y; W[10]=v3.x; W[11]=v3.y;
    }
    u64 ka0,ka1,ka2,ka3, kb0,kb1,kb2,kb3;
    { ulonglong2 t0 = kp2[0], t1 = kp2[1]; kp2 += 2;
      ka0=t0.x; ka1=t0.y; ka2=t1.x; ka3=t1.y; }
    int j = 4*li + 222;
    for (int m = 0; m < 18; ++m) {
        STEPP(4, ka0,ka1,ka2,ka3, kb0,kb1,kb2,kb3);
        STEPP(0, kb0,kb1,kb2,kb3, ka0,ka1,ka2,ka3);
        STEPP(8, ka0,ka1,ka2,ka3, kb0,kb1,kb2,kb3);
        STEPP(4, kb0,kb1,kb2,kb3, ka0,ka1,ka2,ka3);
        STEPP(0, ka0,ka1,ka2,ka3, kb0,kb1,kb2,kb3);
        STEPP(8, kb0,kb1,kb2,kb3, ka0,ka1,ka2,ka3);
    }
    STEPP(4, ka0,ka1,ka2,ka3, kb0,kb1,kb2,kb3);
    STEPP(0, kb0,kb1,kb2,kb3, ka0,ka1,ka2,ka3);
    STEPP(8, ka0,ka1,ka2,ka3, kb0,kb1,kb2,kb3);
    STEPL(4, kb0,kb1,kb2,kb3);

    float4 r0a, r0b, r1a, r1b;
    unpackf2(A0, r0a.x, r1a.x); unpackf2(A1, r0a.y, r1a.y);
    unpackf2(A2, r0a.z, r1a.z); unpackf2(A3, r0a.w, r1a.w);
    unpackf2(A4, r0b.x, r1b.x); unpackf2(A5, r0b.y, r1b.y);
    unpackf2(A6, r0b.z, r1b.z); unpackf2(A7, r0b.w, r1b.w);

    if (WT == 0) {
        float* o0 = out + (size_t)b*NP + (size_t)(y0 + 2*rp)*N + x0;
        ((float4*)o0)[0] = r0a; ((float4*)o0)[1] = r0b;
        ((float4*)(o0 + N))[0] = r1a; ((float4*)(o0 + N))[1] = r1b;
    } else {
        __syncthreads();
        float* stg = (float*)s_in;
        float* sr = stg + (size_t)(2*rp)*STG_PITCH + x0;
        ((float4*)sr)[0] = r0a; ((float4*)sr)[1] = r0b;
        ((float4*)(sr + STG_PITCH))[0] = r1a; ((float4*)(sr + STG_PITCH))[1] = r1b;
        __syncthreads();
        float* ob = out + (size_t)b*NP + y0;
        #pragma unroll
        for (int c = t; c < 448; c += NT) {
            const float* sc = stg + c;
            float4 va;
            va.x = sc[0*STG_PITCH]; va.y = sc[1*STG_PITCH];
            va.z = sc[2*STG_PITCH]; va.w = sc[3*STG_PITCH];
            float* op = ob + (size_t)c*N;
            ((float4*)op)[0] = va;
            if (2*RPB == 8) {
                float4 vb;
                vb.x = sc[4*STG_PITCH]; vb.y = sc[5*STG_PITCH];
                vb.z = sc[6*STG_PITCH]; vb.w = sc[7*STG_PITCH];
                ((float4*)op)[1] = vb;
            }
        }
    }
}

// ---------------- SAD ----------------
__global__ void sad_partial(const float* __restrict__ img1) {
    int blk = blockIdx.x, k = blockIdx.y;
    const float* rot = g_rot + (size_t)k*NP;
    float acc[25];
    #pragma unroll
    for (int q = 0; q < 25; ++q) acc[q] = 0.f;

    int y0 = blk * 26;
    int y1 = (y0 + 26 < 403) ? (y0 + 26) : 403;
    int x = 4 * threadIdx.x;
    int nc = 403 - x; if (nc > 4) nc = 4;

    if (nc > 0) {
        for (int y = y0; y < y1; ++y) {
            const float* r1 = img1 + (size_t)(y + 22)*N + 22 + x;
            float2 p0 = *(const float2*)(r1);
            float2 p1 = *(const float2*)(r1 + 2);
            float v1[4] = {p0.x, p0.y, p1.x, p1.y};
            #pragma unroll
            for (int jj = 0; jj < 5; ++jj) {
                const float* rp = rot + (size_t)(y + 24 - jj)*N + 20 + x;
                float4 fa = *(const float4*)rp;
                float4 fb = *(const float4*)(rp + 4);
                float f[8] = {fa.x, fa.y, fa.z, fa.w, fb.x, fb.y, fb.z, fb.w};
                #pragma unroll
                for (int i = 0; i < 5; ++i) {
                    #pragma unroll
                    for (int c = 0; c < 4; ++c) {
                        float d = fabsf(v1[c] - f[c + 4 - i]);
                        if (c < nc) acc[i*5 + jj] += d;
                    }
                }
            }
        }
    }

    __shared__ double sbin[4][25];
    int w = threadIdx.x >> 5, l = threadIdx.x & 31;
    #pragma unroll
    for (int q = 0; q < 25; ++q) {
        double d = (double)acc[q];
        #pragma unroll
        for (int o = 16; o > 0; o >>= 1)
            d += __shfl_down_sync(0xffffffffu, d, o);
        if (l == 0) sbin[w][q] = d;
    }
    __syncthreads();
    if (threadIdx.x < 25) {
        double s = 0.0;
        #pragma unroll
        for (int w2 = 0; w2 < 4; ++w2) s += sbin[w2][threadIdx.x];
        g_partial[((size_t)k*NSAD_BLK + blk)*25 + threadIdx.x] = s;
    }
}

// merged reduce + argmin + parabolic refinement (single block, 544 threads)
__global__ void sad_final(float* d_out, int off) {
    __shared__ float sad[525];
    int v = threadIdx.x;
    if (v < 525) {
        int k = v % 21, ij = v / 21;
        double s = 0.0;
        for (int b = 0; b < NSAD_BLK; ++b)
            s += g_partial[((size_t)k*NSAD_BLK + b)*25 + ij];
        sad[ij*21 + k] = (float)(s * (1.0 / 162409.0));
    }
    __syncthreads();
    if (threadIdx.x != 0) return;

    float mn = sad[0]; int idx = 0;
    for (int q = 1; q < 525; ++q) {
        float s = sad[q];
        if (s < mn) { mn = s; idx = q; }
    }
    int i = idx / 105, j = (idx / 21) % 5, k = idx % 21;

    float x0 = sad[((i+4)%5)*105 + j*21 + k];
    float x2 = sad[((i+1)%5)*105 + j*21 + k];
    float y0v = sad[i*105 + ((j+4)%5)*21 + k];
    float y2v = sad[i*105 + ((j+1)%5)*21 + k];
    float r0 = sad[i*105 + j*21 + (k+20)%21];
    float r2 = sad[i*105 + j*21 + (k+1)%21];
    float p1 = mn;

    auto pd = [](float a0, float a1, float a2) {
        float a = 0.5f*(a0 + a2) - a1;
        float b = 0.5f*(a2 - a0);
        return -b / (2.0f * a);
    };
    float sx  = (float)(i - 2) + pd(x0, p1, x2);
    float sy  = (float)(j - 2) + pd(y0v, p1, y2v);
    float rot = ((float)(k - 10) + pd(r0, p1, r2)) * (float)(PI_D / 180.0);

    g_res[0] = sx; g_res[1] = sy; g_res[2] = rot;
    if (off >= 3) { d_out[0] = sx; d_out[1] = sy; d_out[2] = rot; }
}

// out = a - b (scalar stores: out may be offset by 3 floats, not 16B-aligned)
__global__ void sub_ab(const float* __restrict__ a, const float* __restrict__ bq,
                       float* __restrict__ out) {
    int i = blockIdx.x * blockDim.x + threadIdx.x;
    if (i < NP/4) {
        float4 va = ((const float4*)a)[i];
        float4 vb = ((const float4*)bq)[i];
        float* op = out + 4*i;
        op[0] = va.x - vb.x;
        op[1] = va.y - vb.y;
        op[2] = va.z - vb.z;
        op[3] = va.w - vb.w;
    }
}

// ---------------- host launch ----------------
extern "C" void kernel_launch(void* const* d_in, const int* in_sizes, int n_in,
                              void* d_out, int out_size) {
    const float* img1 = (const float*)d_in[0];
    const float* img2 = (const float*)d_in[1];
    float* out = (float*)d_out;
    int off = out_size - NP;
    if (off < 0) off = 0;

    float *pA, *pB, *pRot, *pW1, *pW2;
    u64 *pKx3, *pKy3, *pFkp, *pT4p;
    cudaGetSymbolAddress((void**)&pA,   g_A);
    cudaGetSymbolAddress((void**)&pB,   g_B);
    cudaGetSymbolAddress((void**)&pRot, g_rot);
    cudaGetSymbolAddress((void**)&pKx3, g_kxp3);
    cudaGetSymbolAddress((void**)&pKy3, g_kyp3);
    cudaGetSymbolAddress((void**)&pFkp, g_fkp);
    cudaGetSymbolAddress((void**)&pT4p, g_t4p);
    cudaGetSymbolAddress((void**)&pW1,  g_w1);
    cudaGetSymbolAddress((void**)&pW2,  g_w2);

    // 21 rotations via Karatsuba shears: Sx(->T), Sy(->T = normal), Sx(normal)
    build_tables_k<<<dim3(224, NROT, 2), 224>>>();
    shear_k<1><<<dim3(56, NROT), 224>>>(img2, 0,  pA,   pKx3, 0);
    shear_k<1><<<dim3(56, NROT), 224>>>(pA,  NP,  pB,   pKy3, 0);
    shear_k<0><<<dim3(52, NROT), 224>>>(pB,  NP,  pRot, pKx3, 2);  // rows 16..431 only

    // SAD over 525 combos + argmin + refinement (merged)
    sad_partial<<<dim3(NSAD_BLK, NROT), 128>>>(img1);
    sad_final<<<1, 544>>>(out, off);

    // final warp (old-path kernels): rotate then fractional translate
    build_final_all<<<dim3(224, 3), N>>>();
    shear_t<2,1><<<dim3(112, 1), 112>>>(img2, 0, pW1, pFkp,           0, 448);
    shear_t<2,1><<<dim3(112, 1), 112>>>(pW1, 0, pW2, pFkp + 224*448,  0, 448);
    shear_t<2,0><<<dim3(112, 1), 112>>>(pW2, 0, pW1, pFkp,            0, 448);

    shear_t<2,1><<<dim3(112, 2), 112>>>(pW1, 0, pA, pT4p,         448, 0);
    shear_t<2,1><<<dim3(112, 2), 112>>>(pA, NP, pB, pT4p + 2*448, 448, 0);
    sub_ab<<<(NP/4 + 255)/256, 256>>>(pB, pB + NP, out + off);
}

// round 17
// speedup vs baseline: 1.0283x; 1.0283x over previous
#include <cuda_runtime.h>
#include <math.h>

#define N 448
#define NP (N*N)
#define NROT 21
#define NSAD_BLK 16
#define PI_D 3.14159265358979323846

typedef unsigned long long u64;

// ---------------- f32x2 helpers ----------------
#define FMA2(acc, a, b) asm("fma.rn.f32x2 %0, %1, %2, %0;" : "+l"(acc) : "l"(a), "l"(b))
__device__ __forceinline__ u64 packf2(float lo, float hi) {
    u64 r; asm("mov.b64 %0, {%1, %2};" : "=l"(r) : "f"(lo), "f"(hi)); return r;
}
__device__ __forceinline__ void unpackf2(u64 v, float& lo, float& hi) {
    asm("mov.b64 {%0, %1}, %2;" : "=f"(lo), "=f"(hi) : "l"(v));
}

// old swizzle (tail kernel): 64B-per-lane stride granules
#define SWZ(j) ((j) ^ (((j) >> 3) & 3))
// Karatsuba swizzle: 32B-per-lane stride -> 2-way conflict fixed by bit3 parity
#define SWZ2(g) ((g) ^ (((g) >> 3) & 1))

// ---------------- device global scratch ----------------
__device__ __align__(16) float g_A[NROT*NP];
__device__ __align__(16) float g_B[NROT*NP];
__device__ __align__(16) float g_rot[NROT*NP];
__device__ __align__(16) u64   g_kxp3[NROT*224*672];  // [rot][rp][ke|ko|ks] pair streams
__device__ __align__(16) u64   g_kyp3[NROT*224*672];
__device__ __align__(16) u64   g_fkp[2*224*448];      // old-style tables (tail path)
__device__ __align__(16) u64   g_t4p[4*448];
__device__ double g_partial[NROT*NSAD_BLK*25];
__device__ float  g_res[4];
__device__ __align__(16) float g_w1[NP], g_w2[NP];

// ---------------- circulant kernel values ----------------
__device__ __forceinline__ float cr_from(int m, float sf, float S) {
    float w0 = (float)m - sf;
    float w  = (w0 > 224.0f) ? (w0 - 448.0f) : w0;
    if (fabsf(w) < 1e-7f) return 1.0f;
    float num = (m & 1) ? S : -S;
    float arg = w * (1.0f/448.0f);
    return num * cospif(arg) / (448.0f * sinpif(arg));
}
__device__ __forceinline__ float ci_from(int m, float sf, float S) {
    return ((m & 1) ? -S : S) * (1.0f/448.0f);
}
__device__ __forceinline__ int mod_si(double si) {
    int sii = (int)si;
    return ((sii % 448) + 448) % 448;
}

// ---------------- build Karatsuba pair tables: [ke|ko|ks] per row-pair ----------------
__global__ void build_tables_k() {
    __shared__ float sf0, S0, sf1, S1; __shared__ int m00, m01;
    int rp = blockIdx.x, kk = blockIdx.y, type = blockIdx.z;
    if (threadIdx.x < 2) {
        double th = (double)(kk - 10) * (PI_D / 180.0);
        double c  = (type == 0) ? -tan(th * 0.5) : sin(th);
        int row = 2*rp + threadIdx.x;
        double s  = c * ((double)row - 223.5);
        double si = floor(s);
        float sf  = (float)(s - si);
        if (threadIdx.x == 0) { sf0 = sf; S0 = sinpif(sf); m00 = mod_si(si); }
        else                  { sf1 = sf; S1 = sinpif(sf); m01 = mod_si(si); }
    }
    __syncthreads();
    int q = threadIdx.x;               // 0..223
    int ue = 2*q, uo = 2*q + 1;
    int mae = ue - m00; if (mae < 0) mae += 448;
    int mao = uo - m00; if (mao < 0) mao += 448;
    int mbe = ue - m01; if (mbe < 0) mbe += 448;
    int mbo = uo - m01; if (mbo < 0) mbo += 448;
    float ke0 = cr_from(mae, sf0, S0), ko0 = cr_from(mao, sf0, S0);
    float ke1 = cr_from(mbe, sf1, S1), ko1 = cr_from(mbo, sf1, S1);
    u64* dst = ((type == 0) ? g_kxp3 : g_kyp3) + ((size_t)kk*224 + rp)*672;
    dst[q]       = packf2(ke0, ke1);
    dst[224 + q] = packf2(ko0, ko1);
    dst[448 + q] = packf2(ke0 + ko0, ke1 + ko1);
}

// ---------------- merged tail table builder ----------------
__global__ void build_final_all() {
    int type = blockIdx.y;
    if (type < 2) {
        __shared__ float sf0, S0, sf1, S1; __shared__ int m00, m01;
        int rp = blockIdx.x;
        if (threadIdx.x < 2) {
            double th = -(double)g_res[2];
            double c  = (type == 0) ? -tan(th * 0.5) : sin(th);
            int row = 2*rp + threadIdx.x;
            double s  = c * ((double)row - 223.5);
            double si = floor(s);
            float sf  = (float)(s - si);
            if (threadIdx.x == 0) { sf0 = sf; S0 = sinpif(sf); m00 = mod_si(si); }
            else                  { sf1 = sf; S1 = sinpif(sf); m01 = mod_si(si); }
        }
        __syncthreads();
        int u = threadIdx.x;
        int ma = u - m00; if (ma < 0) ma += 448;
        int mb = u - m01; if (mb < 0) mb += 448;
        g_fkp[(size_t)type*224*448 + (size_t)rp*448 + u] =
            packf2(cr_from(ma, sf0, S0), cr_from(mb, sf1, S1));
    } else {
        if (blockIdx.x != 0) return;
        __shared__ float sfx, Sx, sfy, Sy; __shared__ int m0x, m0y;
        if (threadIdx.x == 0) {
            double sx = -(double)g_res[0];
            double sy = -(double)g_res[1];
            double six = floor(sx), siy = floor(sy);
            sfx = (float)(sx - six); Sx = sinpif(sfx); m0x = mod_si(six);
            sfy = (float)(sy - siy); Sy = sinpif(sfy); m0y = mod_si(siy);
        }
        __syncthreads();
        int u = threadIdx.x;
        int mx = u - m0x; if (mx < 0) mx += 448;
        int my = u - m0y; if (my < 0) my += 448;
        float crx = cr_from(mx, sfx, Sx), cix = ci_from(mx, sfx, Sx);
        float cry = cr_from(my, sfy, Sy), ciy = ci_from(my, sfy, Sy);
        g_t4p[0*448 + u] = packf2(crx, crx);
        g_t4p[1*448 + u] = packf2(cix, cix);
        g_t4p[2*448 + u] = packf2(cry, cry);
        g_t4p[3*448 + u] = packf2(ciy, ciy);
    }
}

// ============ Karatsuba conv step macros (taps from smem) ============
// Ring-8 (A/G, 4 accs): loads -> slots (B+t)%8; taps: acc i, c_dd -> slot (B+4+i-dd)%8.
#define CSTEP8(B, P0,P1,P2,P3) do { \
    int sw = su; if (sw >= 224) sw -= 224; \
    int gg = SWZ2(sw >> 1); \
    ulonglong2 va = ip2[gg], vb = ip2[gg ^ 1]; \
    W[((B)+0)%8]=va.x; W[((B)+1)%8]=va.y; W[((B)+2)%8]=vb.x; W[((B)+3)%8]=vb.y; \
    ulonglong2 k01 = kp2[0], k23 = kp2[1]; kp2 += 2; \
    u64 c0=k01.x, c1=k01.y, c2=k23.x, c3=k23.y; \
    FMA2(P0, W[((B)+4)%8], c0); FMA2(P1, W[((B)+5)%8], c0); FMA2(P2, W[((B)+6)%8], c0); FMA2(P3, W[((B)+7)%8], c0); \
    FMA2(P1, W[((B)+4)%8], c1); FMA2(P2, W[((B)+5)%8], c1); FMA2(P3, W[((B)+6)%8], c1); \
    FMA2(P2, W[((B)+4)%8], c2); FMA2(P3, W[((B)+5)%8], c2); \
    FMA2(P3, W[((B)+4)%8], c3); \
    FMA2(P0, W[((B)+3)%8], c1); \
    FMA2(P1, W[((B)+3)%8], c2); FMA2(P0, W[((B)+2)%8], c2); \
    FMA2(P2, W[((B)+3)%8], c3); FMA2(P1, W[((B)+2)%8], c3); FMA2(P0, W[((B)+1)%8], c3); \
    su -= 4; \
} while(0)

// Ring-8 (E, 5 accs targeting p0-1..p0+3): taps: acc i, c_dd -> slot (B+3+i-dd)%8.
#define CSTEP8E(B, Q0,Q1,Q2,Q3,Q4) do { \
    int sw = su; if (sw >= 224) sw -= 224; \
    int gg = SWZ2(sw >> 1); \
    ulonglong2 va = ip2[gg], vb = ip2[gg ^ 1]; \
    W[((B)+0)%8]=va.x; W[((B)+1)%8]=va.y; W[((B)+2)%8]=vb.x; W[((B)+3)%8]=vb.y; \
    ulonglong2 k01 = kp2[0], k23 = kp2[1]; kp2 += 2; \
    u64 c0=k01.x, c1=k01.y, c2=k23.x, c3=k23.y; \
    FMA2(Q1, W[((B)+4)%8], c0); FMA2(Q2, W[((B)+5)%8], c0); FMA2(Q3, W[((B)+6)%8], c0); FMA2(Q4, W[((B)+7)%8], c0); \
    FMA2(Q2, W[((B)+4)%8], c1); FMA2(Q3, W[((B)+5)%8], c1); FMA2(Q4, W[((B)+6)%8], c1); \
    FMA2(Q3, W[((B)+4)%8], c2); FMA2(Q4, W[((B)+5)%8], c2); \
    FMA2(Q4, W[((B)+4)%8], c3); \
    FMA2(Q0, W[((B)+3)%8], c0); \
    FMA2(Q1, W[((B)+3)%8], c1); FMA2(Q0, W[((B)+2)%8], c1); \
    FMA2(Q2, W[((B)+3)%8], c2); FMA2(Q1, W[((B)+2)%8], c2); FMA2(Q0, W[((B)+1)%8], c2); \
    FMA2(Q3, W[((B)+3)%8], c3); FMA2(Q2, W[((B)+2)%8], c3); FMA2(Q1, W[((B)+1)%8], c3); FMA2(Q0, W[((B)+0)%8], c3); \
    su -= 4; \
} while(0)

#define STG_PITCH 456

// ---------------- Karatsuba row-pair shear (RPB=4, 224 threads, 4 blocks/SM) ----------------
// 4 blocks/SM is the verified optimum (R16 showed 5 deepens L1TEX queueing).
template<int WT>
__global__ void __launch_bounds__(224, 4) shear_k(
    const float* __restrict__ in, int inImgStride,
    float* __restrict__ out,
    const u64* __restrict__ tab, int y0off)
{
    __shared__ __align__(16) u64 s_in[4*672];   // per rp: [se|so|ss], each 224 u64, SWZ2
    __shared__ __align__(16) u64 s_k[4*672];    // per rp: [ke|ko|ks]
    int b  = blockIdx.y;
    int bx = blockIdx.x + y0off;
    int y0 = bx * 8;
    int t  = threadIdx.x;

    const float* inb = in + (size_t)b*inImgStride + (size_t)y0*N;
    const u64*   tbb = tab + (size_t)b*(224*672) + (size_t)(bx*4)*672;

    // kernel streams: 4 rp x 336 ulonglong2
    #pragma unroll
    for (int i = t; i < 1344; i += 224) {
        int rp2 = i / 336, jj = i % 336;
        ((ulonglong2*)(s_k + rp2*672))[jj] =
            ((const ulonglong2*)(tbb + (size_t)rp2*672))[jj];
    }
    // input streams: per rp, p in [0,224): se=in[2p], so=in[2p+1], ss=sum
    #pragma unroll
    for (int i = t; i < 896; i += 224) {
        int rp2 = i / 224, p = i % 224;
        const float* r0 = inb + (size_t)(2*rp2)*N;
        float2 a = *(const float2*)(r0 + 2*p);
        float2 c = *(const float2*)(r0 + N + 2*p);
        int g = p >> 1;
        int phys = ((g ^ ((g >> 3) & 1)) << 1) | (p & 1);
        u64* base = s_in + rp2*672;
        base[phys]       = packf2(a.x, c.x);
        base[224 + phys] = packf2(a.y, c.y);
        base[448 + phys] = packf2(a.x + a.y, c.x + c.y);
    }
    __syncthreads();

    int rp = t / 56, li = t % 56;
    int p0 = li * 4;
    int x0 = li * 8;

    u64 W[8];
    u64 A0=0,A1=0,A2=0,A3=0;
    u64 E0=0,E1=0,E2=0,E3=0,E4=0;
    u64 G0=0,G1=0,G2=0,G3=0;
    const ulonglong2* ip2;
    const ulonglong2* kp2;
    int su;
    int gi = SWZ2(p0 >> 1);

    // ---- A = ke (*) se ----
    ip2 = (const ulonglong2*)(s_in + rp*672);
    kp2 = (const ulonglong2*)(s_k + rp*672);
    { ulonglong2 v0 = ip2[gi], v1 = ip2[gi ^ 1];
      W[0]=v0.x; W[1]=v0.y; W[2]=v1.x; W[3]=v1.y; }
    su = p0 + 220;
    for (int m = 0; m < 28; ++m) { CSTEP8(4, A0,A1,A2,A3); CSTEP8(0, A0,A1,A2,A3); }

    // ---- E = ko (*) so  (5 accs: p0-1 .. p0+3), ring-8 ----
    ip2 = (const ulonglong2*)(s_in + rp*672 + 224);
    kp2 = (const ulonglong2*)(s_k + rp*672 + 224);
    { ulonglong2 v0 = ip2[gi], v1 = ip2[gi ^ 1];
      W[0]=v0.x; W[1]=v0.y; W[2]=v1.x; W[3]=v1.y; }
    su = p0 + 220;
    for (int m = 0; m < 28; ++m) { CSTEP8E(4, E0,E1,E2,E3,E4); CSTEP8E(0, E0,E1,E2,E3,E4); }

    // ---- G = ks (*) ss ----
    ip2 = (const ulonglong2*)(s_in + rp*672 + 448);
    kp2 = (const ulonglong2*)(s_k + rp*672 + 448);
    { ulonglong2 v0 = ip2[gi], v1 = ip2[gi ^ 1];
      W[0]=v0.x; W[1]=v0.y; W[2]=v1.x; W[3]=v1.y; }
    su = p0 + 220;
    for (int m = 0; m < 28; ++m) { CSTEP8(4, G0,G1,G2,G3); CSTEP8(0, G0,G1,G2,G3); }

    // ---- combine: out_e[i] = A_i + E_i ; out_o[i] = G_i - A_i - E_{i+1} ----
    float a0l,a0h,a1l,a1h,a2l,a2h,a3l,a3h;
    float e0l,e0h,e1l,e1h,e2l,e2h,e3l,e3h,e4l,e4h;
    float g0l,g0h,g1l,g1h,g2l,g2h,g3l,g3h;
    unpackf2(A0,a0l,a0h); unpackf2(A1,a1l,a1h); unpackf2(A2,a2l,a2h); unpackf2(A3,a3l,a3h);
    unpackf2(E0,e0l,e0h); unpackf2(E1,e1l,e1h); unpackf2(E2,e2l,e2h); unpackf2(E3,e3l,e3h); unpackf2(E4,e4l,e4h);
    unpackf2(G0,g0l,g0h); unpackf2(G1,g1l,g1h); unpackf2(G2,g2l,g2h); unpackf2(G3,g3l,g3h);

    float4 r0a, r0b, r1a, r1b;
    r0a.x = a0l + e0l;  r0a.y = g0l - a0l - e1l;
    r0a.z = a1l + e1l;  r0a.w = g1l - a1l - e2l;
    r0b.x = a2l + e2l;  r0b.y = g2l - a2l - e3l;
    r0b.z = a3l + e3l;  r0b.w = g3l - a3l - e4l;
    r1a.x = a0h + e0h;  r1a.y = g0h - a0h - e1h;
    r1a.z = a1h + e1h;  r1a.w = g1h - a1h - e2h;
    r1b.x = a2h + e2h;  r1b.y = g2h - a2h - e3h;
    r1b.z = a3h + e3h;  r1b.w = g3h - a3h - e4h;

    if (WT == 0) {
        float* o0 = out + (size_t)b*NP + (size_t)(y0 + 2*rp)*N + x0;
        ((float4*)o0)[0] = r0a; ((float4*)o0)[1] = r0b;
        ((float4*)(o0 + N))[0] = r1a; ((float4*)(o0 + N))[1] = r1b;
    } else {
        __syncthreads();
        float* stg = (float*)s_in;
        float* sr = stg + (size_t)(2*rp)*STG_PITCH + x0;
        ((float4*)sr)[0] = r0a; ((float4*)sr)[1] = r0b;
        ((float4*)(sr + STG_PITCH))[0] = r1a; ((float4*)(sr + STG_PITCH))[1] = r1b;
        __syncthreads();
        float* ob = out + (size_t)b*NP + y0;
        #pragma unroll
        for (int c = t; c < 448; c += 224) {
            const float* sc = stg + c;
            float4 va, vb;
            va.x = sc[0*STG_PITCH]; va.y = sc[1*STG_PITCH];
            va.z = sc[2*STG_PITCH]; va.w = sc[3*STG_PITCH];
            vb.x = sc[4*STG_PITCH]; vb.y = sc[5*STG_PITCH];
            vb.z = sc[6*STG_PITCH]; vb.w = sc[7*STG_PITCH];
            float* op = ob + (size_t)c*N;
            ((float4*)op)[0] = va;
            ((float4*)op)[1] = vb;
        }
    }
}

// ---------------- old pipelined shear (tail path, RPB=2) ----------------
#define STEPP(B,c0,c1,c2,c3,n0,n1,n2,n3) do { \
    int sj = SWZ(j); \
    ulonglong2 va = ip2[sj], vb = ip2[sj ^ 1]; \
    { ulonglong2 t0 = kp2[0], t1 = kp2[1]; n0=t0.x; n1=t0.y; n2=t1.x; n3=t1.y; kp2 += 2; } \
    W[((B)+8)%12]=va.x; W[((B)+9)%12]=va.y; W[((B)+10)%12]=vb.x; W[((B)+11)%12]=vb.y; \
    FMA2(A0, W[((B)+12)%12], c0); FMA2(A1, W[((B)+13)%12], c0); FMA2(A2, W[((B)+14)%12], c0); FMA2(A3, W[((B)+15)%12], c0); \
    FMA2(A4, W[((B)+16)%12], c0); FMA2(A5, W[((B)+17)%12], c0); FMA2(A6, W[((B)+18)%12], c0); FMA2(A7, W[((B)+19)%12], c0); \
    FMA2(A1, W[((B)+12)%12], c1); FMA2(A2, W[((B)+13)%12], c1); FMA2(A3, W[((B)+14)%12], c1); FMA2(A4, W[((B)+15)%12], c1); \
    FMA2(A5, W[((B)+16)%12], c1); FMA2(A6, W[((B)+17)%12], c1); FMA2(A7, W[((B)+18)%12], c1); \
    FMA2(A2, W[((B)+12)%12], c2); FMA2(A3, W[((B)+13)%12], c2); FMA2(A4, W[((B)+14)%12], c2); FMA2(A5, W[((B)+15)%12], c2); \
    FMA2(A6, W[((B)+16)%12], c2); FMA2(A7, W[((B)+17)%12], c2); \
    FMA2(A3, W[((B)+12)%12], c3); FMA2(A4, W[((B)+13)%12], c3); FMA2(A5, W[((B)+14)%12], c3); \
    FMA2(A6, W[((B)+15)%12], c3); FMA2(A7, W[((B)+16)%12], c3); \
    FMA2(A0, W[((B)+11)%12], c1); \
    FMA2(A1, W[((B)+11)%12], c2); FMA2(A0, W[((B)+10)%12], c2); \
    FMA2(A2, W[((B)+11)%12], c3); FMA2(A1, W[((B)+10)%12], c3); FMA2(A0, W[((B)+9)%12],  c3); \
    j -= 2; \
} while(0)

#define STEPL(B,c0,c1,c2,c3) do { \
    int sj = SWZ(j); \
    ulonglong2 va = ip2[sj], vb = ip2[sj ^ 1]; \
    W[((B)+8)%12]=va.x; W[((B)+9)%12]=va.y; W[((B)+10)%12]=vb.x; W[((B)+11)%12]=vb.y; \
    FMA2(A0, W[((B)+12)%12], c0); FMA2(A1, W[((B)+13)%12], c0); FMA2(A2, W[((B)+14)%12], c0); FMA2(A3, W[((B)+15)%12], c0); \
    FMA2(A4, W[((B)+16)%12], c0); FMA2(A5, W[((B)+17)%12], c0); FMA2(A6, W[((B)+18)%12], c0); FMA2(A7, W[((B)+19)%12], c0); \
    FMA2(A1, W[((B)+12)%12], c1); FMA2(A2, W[((B)+13)%12], c1); FMA2(A3, W[((B)+14)%12], c1); FMA2(A4, W[((B)+15)%12], c1); \
    FMA2(A5, W[((B)+16)%12], c1); FMA2(A6, W[((B)+17)%12], c1); FMA2(A7, W[((B)+18)%12], c1); \
    FMA2(A2, W[((B)+12)%12], c2); FMA2(A3, W[((B)+13)%12], c2); FMA2(A4, W[((B)+14)%12], c2); FMA2(A5, W[((B)+15)%12], c2); \
    FMA2(A6, W[((B)+16)%12], c2); FMA2(A7, W[((B)+17)%12], c2); \
    FMA2(A3, W[((B)+12)%12], c3); FMA2(A4, W[((B)+13)%12], c3); FMA2(A5, W[((B)+14)%12], c3); \
    FMA2(A6, W[((B)+15)%12], c3); FMA2(A7, W[((B)+16)%12], c3); \
    FMA2(A0, W[((B)+11)%12], c1); \
    FMA2(A1, W[((B)+11)%12], c2); FMA2(A0, W[((B)+10)%12], c2); \
    FMA2(A2, W[((B)+11)%12], c3); FMA2(A1, W[((B)+10)%12], c3); FMA2(A0, W[((B)+9)%12],  c3); \
    j -= 2; \
} while(0)

template<int RPB, int WT>
__global__ void __launch_bounds__(56*RPB, 8) shear_t(
    const float* __restrict__ in, int inImgStride,
    float* __restrict__ out,
    const u64* __restrict__ tab, int tabImgStride, int tabRpStride)
{
    __shared__ __align__(16) u64 s_in[RPB*896];
    __shared__ __align__(16) u64 s_k[RPB*448];
    const int NT = 56*RPB;
    int b  = blockIdx.y;
    int y0 = blockIdx.x * (2*RPB);
    int t  = threadIdx.x;

    const float* inb = in + (size_t)b*inImgStride + (size_t)y0*N;
    const u64*   tbb = tab + (size_t)b*tabImgStride + (size_t)(blockIdx.x*RPB)*tabRpStride;

    #pragma unroll
    for (int idx = t; idx < RPB*224; idx += NT) {
        int rp2 = idx / 224, jj = idx % 224;
        ((ulonglong2*)(s_k + rp2*448))[jj] =
            ((const ulonglong2*)(tbb + (size_t)rp2*tabRpStride))[jj];
    }
    #pragma unroll
    for (int idx = t; idx < RPB*448; idx += NT) {
        int rp2 = idx / 448, j = idx % 448;
        int c0 = 2*j; if (c0 >= 448) c0 -= 448;
        const float* r0 = inb + (size_t)(2*rp2)*N;
        float2 a = *(const float2*)(r0 + c0);
        float2 c = *(const float2*)(r0 + N + c0);
        ulonglong2 p; p.x = packf2(a.x, c.x); p.y = packf2(a.y, c.y);
        ((ulonglong2*)(s_in + rp2*896))[SWZ(j)] = p;
    }
    __syncthreads();

    int rp = t / 56, li = t % 56;
    int x0 = li * 8;
    const ulonglong2* ip2 = (const ulonglong2*)(s_in + rp*896);
    const ulonglong2* kp2 = (const ulonglong2*)(s_k + rp*448);

    u64 A0=0,A1=0,A2=0,A3=0,A4=0,A5=0,A6=0,A7=0;
    u64 W[12];
    {
        int j0 = 4*li + 224;
        int s0 = SWZ(j0);
        ulonglong2 v0 = ip2[s0],     v1 = ip2[s0 ^ 1];
        ulonglong2 v2 = ip2[s0 ^ 2], v3 = ip2[s0 ^ 3];
        W[4]=v0.x; W[5]=v0.y; W[6]=v1.x; W[7]=v1.y;
        W[8]=v2.x; W[9]=v2.y; W[10]=v3.x; W[11]=v3.y;
    }
    u64 ka0,ka1,ka2,ka3, kb0,kb1,kb2,kb3;
    { ulonglong2 t0 = kp2[0], t1 = kp2[1]; kp2 += 2;
      ka0=t0.x; ka1=t0.y; ka2=t1.x; ka3=t1.y; }
    int j = 4*li + 222;
    for (int m = 0; m < 18; ++m) {
        STEPP(4, ka0,ka1,ka2,ka3, kb0,kb1,kb2,kb3);
        STEPP(0, kb0,kb1,kb2,kb3, ka0,ka1,ka2,ka3);
        STEPP(8, ka0,ka1,ka2,ka3, kb0,kb1,kb2,kb3);
        STEPP(4, kb0,kb1,kb2,kb3, ka0,ka1,ka2,ka3);
        STEPP(0, ka0,ka1,ka2,ka3, kb0,kb1,kb2,kb3);
        STEPP(8, kb0,kb1,kb2,kb3, ka0,ka1,ka2,ka3);
    }
    STEPP(4, ka0,ka1,ka2,ka3, kb0,kb1,kb2,kb3);
    STEPP(0, kb0,kb1,kb2,kb3, ka0,ka1,ka2,ka3);
    STEPP(8, ka0,ka1,ka2,ka3, kb0,kb1,kb2,kb3);
    STEPL(4, kb0,kb1,kb2,kb3);

    float4 r0a, r0b, r1a, r1b;
    unpackf2(A0, r0a.x, r1a.x); unpackf2(A1, r0a.y, r1a.y);
    unpackf2(A2, r0a.z, r1a.z); unpackf2(A3, r0a.w, r1a.w);
    unpackf2(A4, r0b.x, r1b.x); unpackf2(A5, r0b.y, r1b.y);
    unpackf2(A6, r0b.z, r1b.z); unpackf2(A7, r0b.w, r1b.w);

    if (WT == 0) {
        float* o0 = out + (size_t)b*NP + (size_t)(y0 + 2*rp)*N + x0;
        ((float4*)o0)[0] = r0a; ((float4*)o0)[1] = r0b;
        ((float4*)(o0 + N))[0] = r1a; ((float4*)(o0 + N))[1] = r1b;
    } else {
        __syncthreads();
        float* stg = (float*)s_in;
        float* sr = stg + (size_t)(2*rp)*STG_PITCH + x0;
        ((float4*)sr)[0] = r0a; ((float4*)sr)[1] = r0b;
        ((float4*)(sr + STG_PITCH))[0] = r1a; ((float4*)(sr + STG_PITCH))[1] = r1b;
        __syncthreads();
        float* ob = out + (size_t)b*NP + y0;
        #pragma unroll
        for (int c = t; c < 448; c += NT) {
            const float* sc = stg + c;
            float4 va;
            va.x = sc[0*STG_PITCH]; va.y = sc[1*STG_PITCH];
            va.z = sc[2*STG_PITCH]; va.w = sc[3*STG_PITCH];
            float* op = ob + (size_t)c*N;
            ((float4*)op)[0] = va;
            if (2*RPB == 8) {
                float4 vb;
                vb.x = sc[4*STG_PITCH]; vb.y = sc[5*STG_PITCH];
                vb.z = sc[6*STG_PITCH]; vb.w = sc[7*STG_PITCH];
                ((float4*)op)[1] = vb;
            }
        }
    }
}

// ---------------- SAD ----------------
__global__ void sad_partial(const float* __restrict__ img1) {
    int blk = blockIdx.x, k = blockIdx.y;
    const float* rot = g_rot + (size_t)k*NP;
    float acc[25];
    #pragma unroll
    for (int q = 0; q < 25; ++q) acc[q] = 0.f;

    int y0 = blk * 26;
    int y1 = (y0 + 26 < 403) ? (y0 + 26) : 403;
    int x = 4 * threadIdx.x;
    int nc = 403 - x; if (nc > 4) nc = 4;

    if (nc > 0) {
        for (int y = y0; y < y1; ++y) {
            const float* r1 = img1 + (size_t)(y + 22)*N + 22 + x;
            float2 p0 = *(const float2*)(r1);
            float2 p1 = *(const float2*)(r1 + 2);
            float v1[4] = {p0.x, p0.y, p1.x, p1.y};
            #pragma unroll
            for (int jj = 0; jj < 5; ++jj) {
                const float* rp = rot + (size_t)(y + 24 - jj)*N + 20 + x;
                float4 fa = *(const float4*)rp;
                float4 fb = *(const float4*)(rp + 4);
                float f[8] = {fa.x, fa.y, fa.z, fa.w, fb.x, fb.y, fb.z, fb.w};
                #pragma unroll
                for (int i = 0; i < 5; ++i) {
                    #pragma unroll
                    for (int c = 0; c < 4; ++c) {
                        float d = fabsf(v1[c] - f[c + 4 - i]);
                        if (c < nc) acc[i*5 + jj] += d;
                    }
                }
            }
        }
    }

    __shared__ double sbin[4][25];
    int w = threadIdx.x >> 5, l = threadIdx.x & 31;
    #pragma unroll
    for (int q = 0; q < 25; ++q) {
        double d = (double)acc[q];
        #pragma unroll
        for (int o = 16; o > 0; o >>= 1)
            d += __shfl_down_sync(0xffffffffu, d, o);
        if (l == 0) sbin[w][q] = d;
    }
    __syncthreads();
    if (threadIdx.x < 25) {
        double s = 0.0;
        #pragma unroll
        for (int w2 = 0; w2 < 4; ++w2) s += sbin[w2][threadIdx.x];
        g_partial[((size_t)k*NSAD_BLK + blk)*25 + threadIdx.x] = s;
    }
}

// merged reduce + argmin + parabolic refinement (single block, 544 threads)
__global__ void sad_final(float* d_out, int off) {
    __shared__ float sad[525];
    int v = threadIdx.x;
    if (v < 525) {
        int k = v % 21, ij = v / 21;
        double s = 0.0;
        for (int b = 0; b < NSAD_BLK; ++b)
            s += g_partial[((size_t)k*NSAD_BLK + b)*25 + ij];
        sad[ij*21 + k] = (float)(s * (1.0 / 162409.0));
    }
    __syncthreads();
    if (threadIdx.x != 0) return;

    float mn = sad[0]; int idx = 0;
    for (int q = 1; q < 525; ++q) {
        float s = sad[q];
        if (s < mn) { mn = s; idx = q; }
    }
    int i = idx / 105, j = (idx / 21) % 5, k = idx % 21;

    float x0 = sad[((i+4)%5)*105 + j*21 + k];
    float x2 = sad[((i+1)%5)*105 + j*21 + k];
    float y0v = sad[i*105 + ((j+4)%5)*21 + k];
    float y2v = sad[i*105 + ((j+1)%5)*21 + k];
    float r0 = sad[i*105 + j*21 + (k+20)%21];
    float r2 = sad[i*105 + j*21 + (k+1)%21];
    float p1 = mn;

    auto pd = [](float a0, float a1, float a2) {
        float a = 0.5f*(a0 + a2) - a1;
        float b = 0.5f*(a2 - a0);
        return -b / (2.0f * a);
    };
    float sx  = (float)(i - 2) + pd(x0, p1, x2);
    float sy  = (float)(j - 2) + pd(y0v, p1, y2v);
    float rot = ((float)(k - 10) + pd(r0, p1, r2)) * (float)(PI_D / 180.0);

    g_res[0] = sx; g_res[1] = sy; g_res[2] = rot;
    if (off >= 3) { d_out[0] = sx; d_out[1] = sy; d_out[2] = rot; }
}

// out = a - b (scalar stores: out may be offset by 3 floats, not 16B-aligned)
__global__ void sub_ab(const float* __restrict__ a, const float* __restrict__ bq,
                       float* __restrict__ out) {
    int i = blockIdx.x * blockDim.x + threadIdx.x;
    if (i < NP/4) {
        float4 va = ((const float4*)a)[i];
        float4 vb = ((const float4*)bq)[i];
        float* op = out + 4*i;
        op[0] = va.x - vb.x;
        op[1] = va.y - vb.y;
        op[2] = va.z - vb.z;
        op[3] = va.w - vb.w;
    }
}

// ---------------- host launch ----------------
extern "C" void kernel_launch(void* const* d_in, const int* in_sizes, int n_in,
                              void* d_out, int out_size) {
    const float* img1 = (const float*)d_in[0];
    const float* img2 = (const float*)d_in[1];
    float* out = (float*)d_out;
    int off = out_size - NP;
    if (off < 0) off = 0;

    float *pA, *pB, *pRot, *pW1, *pW2;
    u64 *pKx3, *pKy3, *pFkp, *pT4p;
    cudaGetSymbolAddress((void**)&pA,   g_A);
    cudaGetSymbolAddress((void**)&pB,   g_B);
    cudaGetSymbolAddress((void**)&pRot, g_rot);
    cudaGetSymbolAddress((void**)&pKx3, g_kxp3);
    cudaGetSymbolAddress((void**)&pKy3, g_kyp3);
    cudaGetSymbolAddress((void**)&pFkp, g_fkp);
    cudaGetSymbolAddress((void**)&pT4p, g_t4p);
    cudaGetSymbolAddress((void**)&pW1,  g_w1);
    cudaGetSymbolAddress((void**)&pW2,  g_w2);

    // 21 rotations via Karatsuba shears: Sx(->T), Sy(->T = normal), Sx(normal)
    build_tables_k<<<dim3(224, NROT, 2), 224>>>();
    shear_k<1><<<dim3(56, NROT), 224>>>(img2, 0,  pA,   pKx3, 0);
    shear_k<1><<<dim3(56, NROT), 224>>>(pA,  NP,  pB,   pKy3, 0);
    shear_k<0><<<dim3(52, NROT), 224>>>(pB,  NP,  pRot, pKx3, 2);  // rows 16..431 only

    // SAD over 525 combos + argmin + refinement (merged)
    sad_partial<<<dim3(NSAD_BLK, NROT), 128>>>(img1);
    sad_final<<<1, 544>>>(out, off);

    // final warp (old-path kernels): rotate then fractional translate
    build_final_all<<<dim3(224, 3), N>>>();
    shear_t<2,1><<<dim3(112, 1), 112>>>(img2, 0, pW1, pFkp,           0, 448);
    shear_t<2,1><<<dim3(112, 1), 112>>>(pW1, 0, pW2, pFkp + 224*448,  0, 448);
    shear_t<2,0><<<dim3(112, 1), 112>>>(pW2, 0, pW1, pFkp,            0, 448);

    shear_t<2,1><<<dim3(112, 2), 112>>>(pW1, 0, pA, pT4p,         448, 0);
    shear_t<2,1><<<dim3(112, 2), 112>>>(pA, NP, pB, pT4p + 2*448, 448, 0);
    sub_ab<<<(NP/4 + 255)/256, 256>>>(pB, pB + NP, out + off);
}